// round 11
// baseline (speedup 1.0000x reference)
#include <cuda_runtime.h>
#include <cuda_bf16.h>
#include <cstdint>

#define NTOK 4096
#define CEMB 128
#define NH 4
#define HD 32
#define NB 4
#define NBH (NB*NH)

// bf16 scratch [bh][n][32]; Q pre-scaled by log2(e)/sqrt(32)
__device__ __align__(16) unsigned short g_Qb[NBH * NTOK * HD];
__device__ __align__(16) unsigned short g_Kb[NBH * NTOK * HD];
__device__ __align__(16) unsigned short g_Vb[NBH * NTOK * HD];

typedef unsigned long long u64;

__device__ __forceinline__ uint32_t smem_u32(const void* p) {
    uint32_t a;
    asm("{ .reg .u64 t; cvta.to.shared.u64 t, %1; cvt.u32.u64 %0, t; }" : "=r"(a) : "l"(p));
    return a;
}
__device__ __forceinline__ float ex2f(float x) {
    float y; asm("ex2.approx.ftz.f32 %0, %1;" : "=f"(y) : "f"(x)); return y;
}
__device__ __forceinline__ uint32_t pack_bf16x2(float hi, float lo) {
    uint32_t r; asm("cvt.rn.bf16x2.f32 %0, %1, %2;" : "=r"(r) : "f"(hi), "f"(lo)); return r;
}
// packed f32x2 (sm_100+; validated working in this harness in R1)
__device__ __forceinline__ u64 ffma2(u64 a, u64 b, u64 c) {
    u64 d; asm("fma.rn.f32x2 %0, %1, %2, %3;" : "=l"(d) : "l"(a), "l"(b), "l"(c)); return d;
}
__device__ __forceinline__ u64 fadd2(u64 a, u64 b) {
    u64 d; asm("add.rn.f32x2 %0, %1, %2;" : "=l"(d) : "l"(a), "l"(b)); return d;
}
__device__ __forceinline__ u64 fmul2(u64 a, u64 b) {
    u64 d; asm("mul.rn.f32x2 %0, %1, %2;" : "=l"(d) : "l"(a), "l"(b)); return d;
}
__device__ __forceinline__ u64 pk2(float x, float y) {
    u64 d; asm("mov.b64 %0, {%1,%2};" : "=l"(d) : "f"(x), "f"(y)); return d;
}
__device__ __forceinline__ float2 upk2(u64 v) {
    float2 r; asm("mov.b64 {%0,%1}, %2;" : "=f"(r.x), "=f"(r.y) : "l"(v)); return r;
}

// FMA-pipe exp2 of a pair: round via magic const, cubic poly, exponent via ALU.
// |err| <= ~6e-4 rel, far below bf16 P-rounding (2^-9).
__device__ __forceinline__ u64 exp2_pair(float x0, float x1) {
    const u64 KC  = pk2(12582912.f, 12582912.f);
    const u64 KNC = pk2(-12582912.f, -12582912.f);
    const u64 KM1 = pk2(-1.f, -1.f);
    const u64 KC3 = pk2(0.05550411f, 0.05550411f);
    const u64 KC2 = pk2(0.24022651f, 0.24022651f);
    const u64 KC1 = pk2(0.69314718f, 0.69314718f);
    const u64 K1  = pk2(1.f, 1.f);
    u64 X = pk2(fmaxf(x0, -100.f), fmaxf(x1, -100.f));
    u64 T = fadd2(X, KC);
    u64 U = fadd2(T, KNC);
    u64 F = ffma2(U, KM1, X);          // f = x - round(x)
    u64 P = ffma2(F, KC3, KC2);
    P = ffma2(F, P, KC1);
    P = ffma2(F, P, K1);
    float2 tf = upk2(T);
    int e0 = (__float_as_int(tf.x) << 23) + 0x3F800000;
    int e1 = (__float_as_int(tf.y) << 23) + 0x3F800000;
    u64 S = pk2(__int_as_float(e0), __int_as_float(e1));
    return fmul2(P, S);
}

#define LDSM4(r0,r1,r2,r3,addr) \
    asm volatile("ldmatrix.sync.aligned.m8n8.x4.shared.b16 {%0,%1,%2,%3}, [%4];" \
        : "=r"(r0),"=r"(r1),"=r"(r2),"=r"(r3) : "r"(addr))
#define LDSM4T(r0,r1,r2,r3,addr) \
    asm volatile("ldmatrix.sync.aligned.m8n8.x4.trans.shared.b16 {%0,%1,%2,%3}, [%4];" \
        : "=r"(r0),"=r"(r1),"=r"(r2),"=r"(r3) : "r"(addr))
#define MMA16816(d, a0,a1,a2,a3, b0,b1) \
    asm volatile("mma.sync.aligned.m16n8k16.row.col.f32.bf16.bf16.f32 " \
        "{%0,%1,%2,%3},{%4,%5,%6,%7},{%8,%9},{%0,%1,%2,%3};" \
        : "+f"((d)[0]),"+f"((d)[1]),"+f"((d)[2]),"+f"((d)[3]) \
        : "r"(a0),"r"(a1),"r"(a2),"r"(a3),"r"(b0),"r"(b1))

#define CP16(dst, src) \
    asm volatile("cp.async.cg.shared.global [%0], [%1], 16;" :: "r"(dst), "l"(src))
#define CPCOMMIT() asm volatile("cp.async.commit_group;" ::: "memory")
#define CPWAIT0()  asm volatile("cp.async.wait_group 0;" ::: "memory")

// ============================================================================
// Kernel 1: QKV projection via bf16 HMMA (unchanged, ~8.5us).
// ============================================================================
__global__ __launch_bounds__(256) void qkv_kernel(
    const float* __restrict__ x,
    const float* __restrict__ W,
    const float* __restrict__ bias)
{
    __shared__ __align__(16) unsigned char xsm[64 * 272];
    __shared__ __align__(16) unsigned char wsm[64 * 272];

    const int t = threadIdx.x;
    const int wid = t >> 5, lane = t & 31;
    const int wm = wid >> 2, wn = wid & 3;
    const int b = blockIdx.z, n0 = blockIdx.y * 128, sect = blockIdx.x;
    const int jg0 = sect * 128;

    const uint32_t xsb = smem_u32(xsm);
    const uint32_t wsb = smem_u32(wsm);

    float acc[4][4][4];
    #pragma unroll
    for (int mt = 0; mt < 4; mt++)
        #pragma unroll
        for (int nt = 0; nt < 4; nt++)
            #pragma unroll
            for (int r = 0; r < 4; r++) acc[mt][nt][r] = 0.f;

    for (int c0 = 0; c0 < 128; c0 += 64) {
        if (c0) __syncthreads();
        #pragma unroll
        for (int r = 0; r < 8; r++) {
            int idx = t + r * 256;
            int cc = idx >> 5, nn4 = (idx & 31) * 4;
            float4 v = *(const float4*)(x + (size_t)b * CEMB * NTOK + (size_t)(c0 + cc) * NTOK + n0 + nn4);
            uint2 pv; pv.x = pack_bf16x2(v.y, v.x); pv.y = pack_bf16x2(v.w, v.z);
            *(uint2*)&xsm[cc * 272 + nn4 * 2] = pv;
            float4 w4 = *(const float4*)(W + (size_t)(c0 + cc) * 384 + jg0 + nn4);
            uint2 pw; pw.x = pack_bf16x2(w4.y, w4.x); pw.y = pack_bf16x2(w4.w, w4.z);
            *(uint2*)&wsm[cc * 272 + nn4 * 2] = pw;
        }
        __syncthreads();

        #pragma unroll
        for (int ks = 0; ks < 4; ks++) {
            int k0 = ks * 16;
            uint32_t af[4][4];
            #pragma unroll
            for (int mt = 0; mt < 4; mt++) {
                uint32_t a = xsb + (uint32_t)(k0 + (lane & 7) + ((lane >> 4) << 3)) * 272
                           + (uint32_t)(wm * 64 + mt * 16 + ((lane >> 3) & 1) * 8) * 2;
                LDSM4T(af[mt][0], af[mt][1], af[mt][2], af[mt][3], a);
            }
            uint32_t bfr[4][2];
            #pragma unroll
            for (int pr = 0; pr < 2; pr++) {
                uint32_t a = wsb + (uint32_t)(k0 + (lane & 7) + (((lane >> 3) & 1) << 3)) * 272
                           + (uint32_t)(wn * 32 + pr * 16 + ((lane >> 4) << 3)) * 2;
                uint32_t r0, r1, r2, r3;
                LDSM4T(r0, r1, r2, r3, a);
                bfr[2*pr][0] = r0; bfr[2*pr][1] = r1;
                bfr[2*pr+1][0] = r2; bfr[2*pr+1][1] = r3;
            }
            #pragma unroll
            for (int mt = 0; mt < 4; mt++)
                #pragma unroll
                for (int nt = 0; nt < 4; nt++)
                    MMA16816(acc[mt][nt], af[mt][0], af[mt][1], af[mt][2], af[mt][3],
                             bfr[nt][0], bfr[nt][1]);
        }
    }

    unsigned short* dst = (sect == 0) ? g_Qb : (sect == 1) ? g_Kb : g_Vb;
    const float sc = (sect == 0) ? 0.25504372842014487f : 1.0f;
    const int bh = b * NH + wn;
    #pragma unroll
    for (int nt = 0; nt < 4; nt++) {
        int jl = wn * 32 + nt * 8 + 2 * (lane & 3);
        float2 bv = *(const float2*)(bias + jg0 + jl);
        int d = jl & 31;
        #pragma unroll
        for (int mt = 0; mt < 4; mt++) {
            int row = n0 + wm * 64 + mt * 16 + (lane >> 2);
            uint32_t w0 = pack_bf16x2((acc[mt][nt][1] + bv.y) * sc, (acc[mt][nt][0] + bv.x) * sc);
            *(uint32_t*)(dst + ((size_t)bh * NTOK + row) * HD + d) = w0;
            uint32_t w1 = pack_bf16x2((acc[mt][nt][3] + bv.y) * sc, (acc[mt][nt][2] + bv.x) * sc);
            *(uint32_t*)(dst + ((size_t)bh * NTOK + row + 8) * HD + d) = w1;
        }
    }
}

// ============================================================================
// Kernel 2: bf16 HMMA flash attention. 128 q/CTA, 2-stage cp.async K/V ring,
// exp split across MUFU (m-tile 0) and FMA-pipe poly (m-tile 1).
// ============================================================================
__global__ __launch_bounds__(128, 4) void attn_kernel(
    const float* __restrict__ x,
    float* __restrict__ out)
{
    __shared__ __align__(128) unsigned char sm[2 * 10240]; // 2 stages x (K 64x80 | V 64x80)

    const int t = threadIdx.x, wid = t >> 5, lane = t & 31;
    const int bh = blockIdx.y, b = bh >> 2, head = bh & 3;
    const int q0 = blockIdx.x * 128;
    const uint32_t smb = smem_u32(sm);

    // ---- stage Q (128 rows x 64B) into stage0 region, load A frags ----
    {
        const uint4* qg = (const uint4*)(g_Qb + ((size_t)bh * NTOK + q0) * HD);
        #pragma unroll
        for (int r = 0; r < 4; r++) {
            int c = t + r * 128;
            *(uint4*)&sm[(c >> 2) * 80 + (c & 3) * 16] = qg[c];
        }
    }
    __syncthreads();
    uint32_t qa[2][2][4];   // [m-tile][k-half][4]
    #pragma unroll
    for (int mt = 0; mt < 2; mt++)
        #pragma unroll
        for (int kh = 0; kh < 2; kh++) {
            uint32_t a = smb + (uint32_t)(32 * wid + 16 * mt + (lane & 15)) * 80 + kh * 32 + (lane >> 4) * 16;
            LDSM4(qa[mt][kh][0], qa[mt][kh][1], qa[mt][kh][2], qa[mt][kh][3], a);
        }
    __syncthreads();

    const char* kgb = (const char*)(g_Kb + (size_t)bh * NTOK * HD);
    const char* vgb = (const char*)(g_Vb + (size_t)bh * NTOK * HD);

    // prologue: issue tile 0 into stage 0 (overwrites Q staging; qa already in regs)
    {
        #pragma unroll
        for (int r = 0; r < 2; r++) {
            int c = t + r * 128;
            uint32_t off = (uint32_t)(c >> 2) * 80 + (c & 3) * 16;
            CP16(smb + off,        kgb + c * 16);
            CP16(smb + 5120 + off, vgb + c * 16);
        }
        CPCOMMIT();
    }

    float o[2][4][4];
    #pragma unroll
    for (int mt = 0; mt < 2; mt++)
        #pragma unroll
        for (int nt = 0; nt < 4; nt++)
            #pragma unroll
            for (int r = 0; r < 4; r++) o[mt][nt][r] = 0.f;
    float ls0[2] = {0.f, 0.f};               // m-tile 0, scalar
    u64 ls1[2] = {pk2(0.f,0.f), pk2(0.f,0.f)}; // m-tile 1, packed

    for (int kt = 0; kt < 64; kt++) {
        const int s = kt & 1;
        CPWAIT0();
        __syncthreads();
        if (kt < 63) {
            const char* kg = kgb + (size_t)(kt + 1) * 4096;
            const char* vg = vgb + (size_t)(kt + 1) * 4096;
            uint32_t base = smb + (uint32_t)(s ^ 1) * 10240;
            #pragma unroll
            for (int r = 0; r < 2; r++) {
                int c = t + r * 128;
                uint32_t off = (uint32_t)(c >> 2) * 80 + (c & 3) * 16;
                CP16(base + off,        kg + c * 16);
                CP16(base + 5120 + off, vg + c * 16);
            }
            CPCOMMIT();
        }

        const uint32_t kst = smb + (uint32_t)s * 10240;
        const uint32_t vst = kst + 5120;

        // ---- S = Q.K^T per 16-key chunk; exp fused (mt0 MUFU, mt1 FMA poly) ----
        uint32_t pp[2][8][2];
        #pragma unroll
        for (int jp = 0; jp < 4; jp++) {
            uint32_t row = jp * 16 + (lane & 7) + ((lane >> 4) << 3);
            uint32_t ch = (lane >> 3) & 1;
            uint32_t b00[4], b01[4];
            LDSM4(b00[0], b00[1], b00[2], b00[3], kst + row * 80 + ch * 16);
            LDSM4(b01[0], b01[1], b01[2], b01[3], kst + row * 80 + (2 + ch) * 16);
            #pragma unroll
            for (int h = 0; h < 2; h++) {
                const int nt = 2 * jp + h;
                // m-tile 0 -> MUFU ex2
                {
                    float s4[4] = {0.f, 0.f, 0.f, 0.f};
                    MMA16816(s4, qa[0][0][0], qa[0][0][1], qa[0][0][2], qa[0][0][3], b00[2*h], b00[2*h+1]);
                    MMA16816(s4, qa[0][1][0], qa[0][1][1], qa[0][1][2], qa[0][1][3], b01[2*h], b01[2*h+1]);
                    float p0 = ex2f(s4[0]), p1 = ex2f(s4[1]), p2 = ex2f(s4[2]), p3 = ex2f(s4[3]);
                    ls0[0] += p0 + p1;
                    ls0[1] += p2 + p3;
                    pp[0][nt][0] = pack_bf16x2(p1, p0);
                    pp[0][nt][1] = pack_bf16x2(p3, p2);
                }
                // m-tile 1 -> FMA-pipe packed poly exp2
                {
                    float s4[4] = {0.f, 0.f, 0.f, 0.f};
                    MMA16816(s4, qa[1][0][0], qa[1][0][1], qa[1][0][2], qa[1][0][3], b00[2*h], b00[2*h+1]);
                    MMA16816(s4, qa[1][1][0], qa[1][1][1], qa[1][1][2], qa[1][1][3], b01[2*h], b01[2*h+1]);
                    u64 r01 = exp2_pair(s4[0], s4[1]);
                    u64 r23 = exp2_pair(s4[2], s4[3]);
                    ls1[0] = fadd2(ls1[0], r01);
                    ls1[1] = fadd2(ls1[1], r23);
                    float2 f01 = upk2(r01);
                    float2 f23 = upk2(r23);
                    pp[1][nt][0] = pack_bf16x2(f01.y, f01.x);
                    pp[1][nt][1] = pack_bf16x2(f23.y, f23.x);
                }
            }
        }

        // ---- O += P.V ----
        #pragma unroll
        for (int k4 = 0; k4 < 4; k4++) {
            uint32_t row = k4 * 16 + (lane & 7) + ((lane >> 3) & 1) * 8;
            uint32_t ch = lane >> 4;
            uint32_t v0[4], v1[4];
            LDSM4T(v0[0], v0[1], v0[2], v0[3], vst + row * 80 + ch * 16);
            LDSM4T(v1[0], v1[1], v1[2], v1[3], vst + row * 80 + (2 + ch) * 16);
            #pragma unroll
            for (int mt = 0; mt < 2; mt++) {
                uint32_t a0 = pp[mt][2*k4][0], a1 = pp[mt][2*k4][1];
                uint32_t a2 = pp[mt][2*k4+1][0], a3 = pp[mt][2*k4+1][1];
                MMA16816(o[mt][0], a0, a1, a2, a3, v0[0], v0[1]);
                MMA16816(o[mt][1], a0, a1, a2, a3, v0[2], v0[3]);
                MMA16816(o[mt][2], a0, a1, a2, a3, v1[0], v1[1]);
                MMA16816(o[mt][3], a0, a1, a2, a3, v1[2], v1[3]);
            }
        }
    }

    // ---- epilogue: row-sum reduce, normalize, residual, write ----
    float lsf[2][2];
    lsf[0][0] = ls0[0]; lsf[0][1] = ls0[1];
    {
        float2 a = upk2(ls1[0]); lsf[1][0] = a.x + a.y;
        float2 c = upk2(ls1[1]); lsf[1][1] = c.x + c.y;
    }
    #pragma unroll
    for (int mt = 0; mt < 2; mt++) {
        float l0 = lsf[mt][0];
        l0 += __shfl_xor_sync(0xffffffffu, l0, 1);
        l0 += __shfl_xor_sync(0xffffffffu, l0, 2);
        float l1 = lsf[mt][1];
        l1 += __shfl_xor_sync(0xffffffffu, l1, 1);
        l1 += __shfl_xor_sync(0xffffffffu, l1, 2);
        float inv0 = 1.0f / l0, inv1 = 1.0f / l1;

        int r0 = q0 + 32 * wid + 16 * mt + (lane >> 2);
        size_t base0 = (size_t)b * (CEMB * NTOK) + (size_t)r0 * CEMB + head * HD;
        size_t base1 = base0 + (size_t)8 * CEMB;

        #pragma unroll
        for (int nt = 0; nt < 4; nt++) {
            int col = 8 * nt + (lane & 3) * 2;
            float2 xv0 = *(const float2*)(x + base0 + col);
            float2 r;
            r.x = fmaf(o[mt][nt][0], inv0, xv0.x);
            r.y = fmaf(o[mt][nt][1], inv0, xv0.y);
            *(float2*)(out + base0 + col) = r;
            float2 xv1 = *(const float2*)(x + base1 + col);
            r.x = fmaf(o[mt][nt][2], inv1, xv1.x);
            r.y = fmaf(o[mt][nt][3], inv1, xv1.y);
            *(float2*)(out + base1 + col) = r;
        }
    }
}

extern "C" void kernel_launch(void* const* d_in, const int* in_sizes, int n_in,
                              void* d_out, int out_size) {
    const float* x    = (const float*)d_in[0];
    const float* W    = (const float*)d_in[1];
    const float* bias = (const float*)d_in[2];
    float* out = (float*)d_out;

    dim3 g1(3, 32, NB);
    qkv_kernel<<<g1, 256>>>(x, W, bias);

    dim3 g2(NTOK / 128, NBH);
    attn_kernel<<<g2, 128>>>(x, out);
}

// round 15
// speedup vs baseline: 1.2453x; 1.2453x over previous
#include <cuda_runtime.h>
#include <cuda_bf16.h>
#include <cuda_fp16.h>
#include <cstdint>

#define NTOK 4096
#define CEMB 128
#define NH 4
#define HD 32
#define NB 4
#define NBH (NB*NH)

// fp16 scratch [bh][n][32]; Q pre-scaled by log2(e)/sqrt(32)
__device__ __align__(16) unsigned short g_Qb[NBH * NTOK * HD];
__device__ __align__(16) unsigned short g_Kb[NBH * NTOK * HD];
__device__ __align__(16) unsigned short g_Vb[NBH * NTOK * HD];

__device__ __forceinline__ uint32_t smem_u32(const void* p) {
    uint32_t a;
    asm("{ .reg .u64 t; cvta.to.shared.u64 t, %1; cvt.u32.u64 %0, t; }" : "=r"(a) : "l"(p));
    return a;
}
__device__ __forceinline__ uint32_t pack_f16x2(float hi, float lo) {
    uint32_t r; asm("cvt.rn.f16x2.f32 %0, %1, %2;" : "=r"(r) : "f"(hi), "f"(lo)); return r;
}
__device__ __forceinline__ uint32_t ex2_h2(uint32_t x) {
    uint32_t y; asm("ex2.approx.f16x2 %0, %1;" : "=r"(y) : "r"(x)); return y;
}
__device__ __forceinline__ uint32_t hadd2(uint32_t a, uint32_t b) {
    uint32_t d; asm("add.rn.f16x2 %0, %1, %2;" : "=r"(d) : "r"(a), "r"(b)); return d;
}
__device__ __forceinline__ float2 h2_to_f2(uint32_t h) {
    float lo, hi;
    asm("{ .reg .f16 a, b; mov.b32 {a, b}, %2; cvt.f32.f16 %0, a; cvt.f32.f16 %1, b; }"
        : "=f"(lo), "=f"(hi) : "r"(h));
    return make_float2(lo, hi);
}

#define LDSM4(r0,r1,r2,r3,addr) \
    asm volatile("ldmatrix.sync.aligned.m8n8.x4.shared.b16 {%0,%1,%2,%3}, [%4];" \
        : "=r"(r0),"=r"(r1),"=r"(r2),"=r"(r3) : "r"(addr))
#define LDSM4T(r0,r1,r2,r3,addr) \
    asm volatile("ldmatrix.sync.aligned.m8n8.x4.trans.shared.b16 {%0,%1,%2,%3}, [%4];" \
        : "=r"(r0),"=r"(r1),"=r"(r2),"=r"(r3) : "r"(addr))
#define MMA16816(d, a0,a1,a2,a3, b0,b1) \
    asm volatile("mma.sync.aligned.m16n8k16.row.col.f32.f16.f16.f32 " \
        "{%0,%1,%2,%3},{%4,%5,%6,%7},{%8,%9},{%0,%1,%2,%3};" \
        : "+f"((d)[0]),"+f"((d)[1]),"+f"((d)[2]),"+f"((d)[3]) \
        : "r"(a0),"r"(a1),"r"(a2),"r"(a3),"r"(b0),"r"(b1))

#define CP16(dst, src) \
    asm volatile("cp.async.cg.shared.global [%0], [%1], 16;" :: "r"(dst), "l"(src))
#define CPCOMMIT() asm volatile("cp.async.commit_group;" ::: "memory")
#define CPWAIT0()  asm volatile("cp.async.wait_group 0;" ::: "memory")

// ============================================================================
// Kernel 1: QKV projection via fp16 HMMA.
// ============================================================================
__global__ __launch_bounds__(256) void qkv_kernel(
    const float* __restrict__ x,
    const float* __restrict__ W,
    const float* __restrict__ bias)
{
    __shared__ __align__(16) unsigned char xsm[64 * 272];
    __shared__ __align__(16) unsigned char wsm[64 * 272];

    const int t = threadIdx.x;
    const int wid = t >> 5, lane = t & 31;
    const int wm = wid >> 2, wn = wid & 3;
    const int b = blockIdx.z, n0 = blockIdx.y * 128, sect = blockIdx.x;
    const int jg0 = sect * 128;

    const uint32_t xsb = smem_u32(xsm);
    const uint32_t wsb = smem_u32(wsm);

    float acc[4][4][4];
    #pragma unroll
    for (int mt = 0; mt < 4; mt++)
        #pragma unroll
        for (int nt = 0; nt < 4; nt++)
            #pragma unroll
            for (int r = 0; r < 4; r++) acc[mt][nt][r] = 0.f;

    for (int c0 = 0; c0 < 128; c0 += 64) {
        if (c0) __syncthreads();
        #pragma unroll
        for (int r = 0; r < 8; r++) {
            int idx = t + r * 256;
            int cc = idx >> 5, nn4 = (idx & 31) * 4;
            float4 v = *(const float4*)(x + (size_t)b * CEMB * NTOK + (size_t)(c0 + cc) * NTOK + n0 + nn4);
            uint2 pv; pv.x = pack_f16x2(v.y, v.x); pv.y = pack_f16x2(v.w, v.z);
            *(uint2*)&xsm[cc * 272 + nn4 * 2] = pv;
            float4 w4 = *(const float4*)(W + (size_t)(c0 + cc) * 384 + jg0 + nn4);
            uint2 pw; pw.x = pack_f16x2(w4.y, w4.x); pw.y = pack_f16x2(w4.w, w4.z);
            *(uint2*)&wsm[cc * 272 + nn4 * 2] = pw;
        }
        __syncthreads();

        #pragma unroll
        for (int ks = 0; ks < 4; ks++) {
            int k0 = ks * 16;
            uint32_t af[4][4];
            #pragma unroll
            for (int mt = 0; mt < 4; mt++) {
                uint32_t a = xsb + (uint32_t)(k0 + (lane & 7) + ((lane >> 4) << 3)) * 272
                           + (uint32_t)(wm * 64 + mt * 16 + ((lane >> 3) & 1) * 8) * 2;
                LDSM4T(af[mt][0], af[mt][1], af[mt][2], af[mt][3], a);
            }
            uint32_t bfr[4][2];
            #pragma unroll
            for (int pr = 0; pr < 2; pr++) {
                uint32_t a = wsb + (uint32_t)(k0 + (lane & 7) + (((lane >> 3) & 1) << 3)) * 272
                           + (uint32_t)(wn * 32 + pr * 16 + ((lane >> 4) << 3)) * 2;
                uint32_t r0, r1, r2, r3;
                LDSM4T(r0, r1, r2, r3, a);
                bfr[2*pr][0] = r0; bfr[2*pr][1] = r1;
                bfr[2*pr+1][0] = r2; bfr[2*pr+1][1] = r3;
            }
            #pragma unroll
            for (int mt = 0; mt < 4; mt++)
                #pragma unroll
                for (int nt = 0; nt < 4; nt++)
                    MMA16816(acc[mt][nt], af[mt][0], af[mt][1], af[mt][2], af[mt][3],
                             bfr[nt][0], bfr[nt][1]);
        }
    }

    unsigned short* dst = (sect == 0) ? g_Qb : (sect == 1) ? g_Kb : g_Vb;
    const float sc = (sect == 0) ? 0.25504372842014487f : 1.0f;  // log2(e)/sqrt(32)
    const int bh = b * NH + wn;
    #pragma unroll
    for (int nt = 0; nt < 4; nt++) {
        int jl = wn * 32 + nt * 8 + 2 * (lane & 3);
        float2 bv = *(const float2*)(bias + jg0 + jl);
        int d = jl & 31;
        #pragma unroll
        for (int mt = 0; mt < 4; mt++) {
            int row = n0 + wm * 64 + mt * 16 + (lane >> 2);
            uint32_t w0 = pack_f16x2((acc[mt][nt][1] + bv.y) * sc, (acc[mt][nt][0] + bv.x) * sc);
            *(uint32_t*)(dst + ((size_t)bh * NTOK + row) * HD + d) = w0;
            uint32_t w1 = pack_f16x2((acc[mt][nt][3] + bv.y) * sc, (acc[mt][nt][2] + bv.x) * sc);
            *(uint32_t*)(dst + ((size_t)bh * NTOK + row + 8) * HD + d) = w1;
        }
    }
}

// ============================================================================
// Kernel 2: fp16 HMMA flash attention, 64 q/CTA, 2-stage cp.async ring.
// Per 16-key group: S-MMA -> ex2.f16x2 (P directly in A-frag layout) -> PV-MMA.
// ============================================================================
__global__ __launch_bounds__(128, 5) void attn_kernel(
    const float* __restrict__ x,
    float* __restrict__ out)
{
    __shared__ __align__(128) unsigned char sm[20480];  // 2 stages x (K 64x80 | V 64x80)

    const int t = threadIdx.x, wid = t >> 5, lane = t & 31;
    const int bh = blockIdx.y, b = bh >> 2, head = bh & 3;
    const int q0 = blockIdx.x * 64;
    const uint32_t smb = smem_u32(sm);

    // ---- stage Q (64 rows x 64B) and load A fragments ----
    {
        const uint4* qg = (const uint4*)(g_Qb + ((size_t)bh * NTOK + q0) * HD);
        #pragma unroll
        for (int r = 0; r < 2; r++) {
            int c = t + r * 128;
            *(uint4*)&sm[(c >> 2) * 80 + (c & 3) * 16] = qg[c];
        }
    }
    __syncthreads();
    uint32_t qa[2][4];
    #pragma unroll
    for (int kh = 0; kh < 2; kh++) {
        uint32_t a = smb + (uint32_t)(16 * wid + (lane & 15)) * 80 + kh * 32 + (lane >> 4) * 16;
        LDSM4(qa[kh][0], qa[kh][1], qa[kh][2], qa[kh][3], a);
    }
    __syncthreads();

    float o[4][4];
    #pragma unroll
    for (int nt = 0; nt < 4; nt++)
        #pragma unroll
        for (int r = 0; r < 4; r++) o[nt][r] = 0.f;
    float lsum[2] = {0.f, 0.f};

    const char* kgb = (const char*)(g_Kb + (size_t)bh * NTOK * HD);
    const char* vgb = (const char*)(g_Vb + (size_t)bh * NTOK * HD);

    // prologue: issue tile 0 into stage 0
    {
        #pragma unroll
        for (int r = 0; r < 2; r++) {
            int c = t + r * 128;
            uint32_t off = (uint32_t)(c >> 2) * 80 + (c & 3) * 16;
            CP16(smb + off,        kgb + c * 16);
            CP16(smb + 5120 + off, vgb + c * 16);
        }
        CPCOMMIT();
    }

    for (int kt = 0; kt < 64; kt++) {
        const int s = kt & 1;
        CPWAIT0();
        __syncthreads();
        if (kt < 63) {
            const char* kg = kgb + (size_t)(kt + 1) * 4096;
            const char* vg = vgb + (size_t)(kt + 1) * 4096;
            uint32_t base = smb + (uint32_t)(s ^ 1) * 10240;
            #pragma unroll
            for (int r = 0; r < 2; r++) {
                int c = t + r * 128;
                uint32_t off = (uint32_t)(c >> 2) * 80 + (c & 3) * 16;
                CP16(base + off,        kg + c * 16);
                CP16(base + 5120 + off, vg + c * 16);
            }
            CPCOMMIT();
        }

        const uint32_t kst = smb + (uint32_t)s * 10240;
        const uint32_t vst = kst + 5120;

        // ---- per 16-key group: S -> exp (f16x2) -> PV ----
        #pragma unroll
        for (int g = 0; g < 4; g++) {
            uint32_t rowk = g * 16 + (lane & 7) + ((lane >> 4) << 3);
            uint32_t chk = (lane >> 3) & 1;
            uint32_t b00[4], b01[4];
            LDSM4(b00[0], b00[1], b00[2], b00[3], kst + rowk * 80 + chk * 16);
            LDSM4(b01[0], b01[1], b01[2], b01[3], kst + rowk * 80 + (2 + chk) * 16);

            uint32_t A[4];   // P in fp16 A-fragment layout
            #pragma unroll
            for (int h = 0; h < 2; h++) {
                float s4[4] = {0.f, 0.f, 0.f, 0.f};
                MMA16816(s4, qa[0][0], qa[0][1], qa[0][2], qa[0][3], b00[2*h], b00[2*h+1]);
                MMA16816(s4, qa[1][0], qa[1][1], qa[1][2], qa[1][3], b01[2*h], b01[2*h+1]);
                A[2*h]   = ex2_h2(pack_f16x2(s4[1], s4[0]));
                A[2*h+1] = ex2_h2(pack_f16x2(s4[3], s4[2]));
            }
            // l-sum: row r = A[0]+A[2], row r+8 = A[1]+A[3] (f16 adds of 2 small vals)
            float2 f0 = h2_to_f2(hadd2(A[0], A[2]));
            lsum[0] += f0.x + f0.y;
            float2 f1 = h2_to_f2(hadd2(A[1], A[3]));
            lsum[1] += f1.x + f1.y;

            uint32_t rowv = g * 16 + (lane & 7) + ((lane >> 3) & 1) * 8;
            uint32_t chv = lane >> 4;
            uint32_t v0[4], v1[4];
            LDSM4T(v0[0], v0[1], v0[2], v0[3], vst + rowv * 80 + chv * 16);
            LDSM4T(v1[0], v1[1], v1[2], v1[3], vst + rowv * 80 + (2 + chv) * 16);
            MMA16816(o[0], A[0], A[1], A[2], A[3], v0[0], v0[1]);
            MMA16816(o[1], A[0], A[1], A[2], A[3], v0[2], v0[3]);
            MMA16816(o[2], A[0], A[1], A[2], A[3], v1[0], v1[1]);
            MMA16816(o[3], A[0], A[1], A[2], A[3], v1[2], v1[3]);
        }
    }

    // ---- epilogue: row-sum reduce, normalize, residual, write ----
    float l0 = lsum[0];
    l0 += __shfl_xor_sync(0xffffffffu, l0, 1);
    l0 += __shfl_xor_sync(0xffffffffu, l0, 2);
    float l1 = lsum[1];
    l1 += __shfl_xor_sync(0xffffffffu, l1, 1);
    l1 += __shfl_xor_sync(0xffffffffu, l1, 2);
    float inv0 = 1.0f / l0, inv1 = 1.0f / l1;

    int r0 = q0 + 16 * wid + (lane >> 2);
    size_t base0 = (size_t)b * (CEMB * NTOK) + (size_t)r0 * CEMB + head * HD;
    size_t base1 = base0 + (size_t)8 * CEMB;

    #pragma unroll
    for (int nt = 0; nt < 4; nt++) {
        int col = 8 * nt + (lane & 3) * 2;
        float2 xv0 = *(const float2*)(x + base0 + col);
        float2 r;
        r.x = fmaf(o[nt][0], inv0, xv0.x);
        r.y = fmaf(o[nt][1], inv0, xv0.y);
        *(float2*)(out + base0 + col) = r;
        float2 xv1 = *(const float2*)(x + base1 + col);
        r.x = fmaf(o[nt][2], inv1, xv1.x);
        r.y = fmaf(o[nt][3], inv1, xv1.y);
        *(float2*)(out + base1 + col) = r;
    }
}

extern "C" void kernel_launch(void* const* d_in, const int* in_sizes, int n_in,
                              void* d_out, int out_size) {
    const float* x    = (const float*)d_in[0];
    const float* W    = (const float*)d_in[1];
    const float* bias = (const float*)d_in[2];
    float* out = (float*)d_out;

    dim3 g1(3, 32, NB);
    qkv_kernel<<<g1, 256>>>(x, W, bias);

    dim3 g2(NTOK / 64, NBH);
    attn_kernel<<<g2, 128>>>(x, out);
}

// round 16
// speedup vs baseline: 1.2679x; 1.0181x over previous
#include <cuda_runtime.h>
#include <cuda_bf16.h>
#include <cuda_fp16.h>
#include <cstdint>

#define NTOK 4096
#define CEMB 128
#define NH 4
#define HD 32
#define NB 4
#define NBH (NB*NH)

// fp16 scratch [bh][n][32]; Q pre-scaled by log2(e)/sqrt(32)
__device__ __align__(16) unsigned short g_Qb[NBH * NTOK * HD];
__device__ __align__(16) unsigned short g_Kb[NBH * NTOK * HD];
__device__ __align__(16) unsigned short g_Vb[NBH * NTOK * HD];

__device__ __forceinline__ uint32_t smem_u32(const void* p) {
    uint32_t a;
    asm("{ .reg .u64 t; cvta.to.shared.u64 t, %1; cvt.u32.u64 %0, t; }" : "=r"(a) : "l"(p));
    return a;
}
__device__ __forceinline__ uint32_t pack_f16x2(float hi, float lo) {
    uint32_t r; asm("cvt.rn.f16x2.f32 %0, %1, %2;" : "=r"(r) : "f"(hi), "f"(lo)); return r;
}
__device__ __forceinline__ uint32_t ex2_h2(uint32_t x) {
    uint32_t y; asm("ex2.approx.f16x2 %0, %1;" : "=r"(y) : "r"(x)); return y;
}
__device__ __forceinline__ uint32_t hadd2(uint32_t a, uint32_t b) {
    uint32_t d; asm("add.rn.f16x2 %0, %1, %2;" : "=r"(d) : "r"(a), "r"(b)); return d;
}
__device__ __forceinline__ float2 h2_to_f2(uint32_t h) {
    float lo, hi;
    asm("{ .reg .f16 a, b; mov.b32 {a, b}, %2; cvt.f32.f16 %0, a; cvt.f32.f16 %1, b; }"
        : "=f"(lo), "=f"(hi) : "r"(h));
    return make_float2(lo, hi);
}

#define LDSM4(r0,r1,r2,r3,addr) \
    asm volatile("ldmatrix.sync.aligned.m8n8.x4.shared.b16 {%0,%1,%2,%3}, [%4];" \
        : "=r"(r0),"=r"(r1),"=r"(r2),"=r"(r3) : "r"(addr))
#define LDSM4T(r0,r1,r2,r3,addr) \
    asm volatile("ldmatrix.sync.aligned.m8n8.x4.trans.shared.b16 {%0,%1,%2,%3}, [%4];" \
        : "=r"(r0),"=r"(r1),"=r"(r2),"=r"(r3) : "r"(addr))
#define MMA16816(d, a0,a1,a2,a3, b0,b1) \
    asm volatile("mma.sync.aligned.m16n8k16.row.col.f32.f16.f16.f32 " \
        "{%0,%1,%2,%3},{%4,%5,%6,%7},{%8,%9},{%0,%1,%2,%3};" \
        : "+f"((d)[0]),"+f"((d)[1]),"+f"((d)[2]),"+f"((d)[3]) \
        : "r"(a0),"r"(a1),"r"(a2),"r"(a3),"r"(b0),"r"(b1))

#define CP16(dst, src) \
    asm volatile("cp.async.cg.shared.global [%0], [%1], 16;" :: "r"(dst), "l"(src))
#define CPCOMMIT() asm volatile("cp.async.commit_group;" ::: "memory")
#define CPWAIT0()  asm volatile("cp.async.wait_group 0;" ::: "memory")

// ============================================================================
// Kernel 1: QKV projection via fp16 HMMA (unchanged from R15).
// ============================================================================
__global__ __launch_bounds__(256) void qkv_kernel(
    const float* __restrict__ x,
    const float* __restrict__ W,
    const float* __restrict__ bias)
{
    __shared__ __align__(16) unsigned char xsm[64 * 272];
    __shared__ __align__(16) unsigned char wsm[64 * 272];

    const int t = threadIdx.x;
    const int wid = t >> 5, lane = t & 31;
    const int wm = wid >> 2, wn = wid & 3;
    const int b = blockIdx.z, n0 = blockIdx.y * 128, sect = blockIdx.x;
    const int jg0 = sect * 128;

    const uint32_t xsb = smem_u32(xsm);
    const uint32_t wsb = smem_u32(wsm);

    float acc[4][4][4];
    #pragma unroll
    for (int mt = 0; mt < 4; mt++)
        #pragma unroll
        for (int nt = 0; nt < 4; nt++)
            #pragma unroll
            for (int r = 0; r < 4; r++) acc[mt][nt][r] = 0.f;

    for (int c0 = 0; c0 < 128; c0 += 64) {
        if (c0) __syncthreads();
        #pragma unroll
        for (int r = 0; r < 8; r++) {
            int idx = t + r * 256;
            int cc = idx >> 5, nn4 = (idx & 31) * 4;
            float4 v = *(const float4*)(x + (size_t)b * CEMB * NTOK + (size_t)(c0 + cc) * NTOK + n0 + nn4);
            uint2 pv; pv.x = pack_f16x2(v.y, v.x); pv.y = pack_f16x2(v.w, v.z);
            *(uint2*)&xsm[cc * 272 + nn4 * 2] = pv;
            float4 w4 = *(const float4*)(W + (size_t)(c0 + cc) * 384 + jg0 + nn4);
            uint2 pw; pw.x = pack_f16x2(w4.y, w4.x); pw.y = pack_f16x2(w4.w, w4.z);
            *(uint2*)&wsm[cc * 272 + nn4 * 2] = pw;
        }
        __syncthreads();

        #pragma unroll
        for (int ks = 0; ks < 4; ks++) {
            int k0 = ks * 16;
            uint32_t af[4][4];
            #pragma unroll
            for (int mt = 0; mt < 4; mt++) {
                uint32_t a = xsb + (uint32_t)(k0 + (lane & 7) + ((lane >> 4) << 3)) * 272
                           + (uint32_t)(wm * 64 + mt * 16 + ((lane >> 3) & 1) * 8) * 2;
                LDSM4T(af[mt][0], af[mt][1], af[mt][2], af[mt][3], a);
            }
            uint32_t bfr[4][2];
            #pragma unroll
            for (int pr = 0; pr < 2; pr++) {
                uint32_t a = wsb + (uint32_t)(k0 + (lane & 7) + (((lane >> 3) & 1) << 3)) * 272
                           + (uint32_t)(wn * 32 + pr * 16 + ((lane >> 4) << 3)) * 2;
                uint32_t r0, r1, r2, r3;
                LDSM4T(r0, r1, r2, r3, a);
                bfr[2*pr][0] = r0; bfr[2*pr][1] = r1;
                bfr[2*pr+1][0] = r2; bfr[2*pr+1][1] = r3;
            }
            #pragma unroll
            for (int mt = 0; mt < 4; mt++)
                #pragma unroll
                for (int nt = 0; nt < 4; nt++)
                    MMA16816(acc[mt][nt], af[mt][0], af[mt][1], af[mt][2], af[mt][3],
                             bfr[nt][0], bfr[nt][1]);
        }
    }

    unsigned short* dst = (sect == 0) ? g_Qb : (sect == 1) ? g_Kb : g_Vb;
    const float sc = (sect == 0) ? 0.25504372842014487f : 1.0f;  // log2(e)/sqrt(32)
    const int bh = b * NH + wn;
    #pragma unroll
    for (int nt = 0; nt < 4; nt++) {
        int jl = wn * 32 + nt * 8 + 2 * (lane & 3);
        float2 bv = *(const float2*)(bias + jg0 + jl);
        int d = jl & 31;
        #pragma unroll
        for (int mt = 0; mt < 4; mt++) {
            int row = n0 + wm * 64 + mt * 16 + (lane >> 2);
            uint32_t w0 = pack_f16x2((acc[mt][nt][1] + bv.y) * sc, (acc[mt][nt][0] + bv.x) * sc);
            *(uint32_t*)(dst + ((size_t)bh * NTOK + row) * HD + d) = w0;
            uint32_t w1 = pack_f16x2((acc[mt][nt][3] + bv.y) * sc, (acc[mt][nt][2] + bv.x) * sc);
            *(uint32_t*)(dst + ((size_t)bh * NTOK + row + 8) * HD + d) = w1;
        }
    }
}

// ============================================================================
// Kernel 2: fp16 HMMA flash attention. 128 q/CTA (2 m-tiles/warp) so K/V LDSM
// traffic is amortized over 2x MMAs; 2-stage cp.async ring; per 16-key group:
// S -> ex2.f16x2 (P directly in A-frag layout) -> PV for both m-tiles.
// ============================================================================
__global__ __launch_bounds__(128, 4) void attn_kernel(
    const float* __restrict__ x,
    float* __restrict__ out)
{
    __shared__ __align__(128) unsigned char sm[20480];  // 2 stages x (K 64x80 | V 64x80)

    const int t = threadIdx.x, wid = t >> 5, lane = t & 31;
    const int bh = blockIdx.y, b = bh >> 2, head = bh & 3;
    const int q0 = blockIdx.x * 128;
    const uint32_t smb = smem_u32(sm);

    // ---- stage Q (128 rows x 64B) across both stages, load A frags ----
    {
        const uint4* qg = (const uint4*)(g_Qb + ((size_t)bh * NTOK + q0) * HD);
        #pragma unroll
        for (int r = 0; r < 4; r++) {
            int c = t + r * 128;
            *(uint4*)&sm[(c >> 2) * 80 + (c & 3) * 16] = qg[c];
        }
    }
    __syncthreads();
    uint32_t qa[2][2][4];   // [m-tile][k-half][4]
    #pragma unroll
    for (int mt = 0; mt < 2; mt++)
        #pragma unroll
        for (int kh = 0; kh < 2; kh++) {
            uint32_t a = smb + (uint32_t)(32 * wid + 16 * mt + (lane & 15)) * 80 + kh * 32 + (lane >> 4) * 16;
            LDSM4(qa[mt][kh][0], qa[mt][kh][1], qa[mt][kh][2], qa[mt][kh][3], a);
        }
    __syncthreads();

    float o[2][4][4];
    #pragma unroll
    for (int mt = 0; mt < 2; mt++)
        #pragma unroll
        for (int nt = 0; nt < 4; nt++)
            #pragma unroll
            for (int r = 0; r < 4; r++) o[mt][nt][r] = 0.f;
    float lsum[2][2] = {{0.f, 0.f}, {0.f, 0.f}};

    const char* kgb = (const char*)(g_Kb + (size_t)bh * NTOK * HD);
    const char* vgb = (const char*)(g_Vb + (size_t)bh * NTOK * HD);

    // prologue: issue tile 0 into stage 0 (overwrites Q staging; qa in regs)
    {
        #pragma unroll
        for (int r = 0; r < 2; r++) {
            int c = t + r * 128;
            uint32_t off = (uint32_t)(c >> 2) * 80 + (c & 3) * 16;
            CP16(smb + off,        kgb + c * 16);
            CP16(smb + 5120 + off, vgb + c * 16);
        }
        CPCOMMIT();
    }

    for (int kt = 0; kt < 64; kt++) {
        const int s = kt & 1;
        CPWAIT0();
        __syncthreads();
        if (kt < 63) {
            const char* kg = kgb + (size_t)(kt + 1) * 4096;
            const char* vg = vgb + (size_t)(kt + 1) * 4096;
            uint32_t base = smb + (uint32_t)(s ^ 1) * 10240;
            #pragma unroll
            for (int r = 0; r < 2; r++) {
                int c = t + r * 128;
                uint32_t off = (uint32_t)(c >> 2) * 80 + (c & 3) * 16;
                CP16(base + off,        kg + c * 16);
                CP16(base + 5120 + off, vg + c * 16);
            }
            CPCOMMIT();
        }

        const uint32_t kst = smb + (uint32_t)s * 10240;
        const uint32_t vst = kst + 5120;

        // ---- per 16-key group: S (both m-tiles) -> exp -> PV (both m-tiles) ----
        #pragma unroll
        for (int g = 0; g < 4; g++) {
            uint32_t rowk = g * 16 + (lane & 7) + ((lane >> 4) << 3);
            uint32_t chk = (lane >> 3) & 1;
            uint32_t b00[4], b01[4];
            LDSM4(b00[0], b00[1], b00[2], b00[3], kst + rowk * 80 + chk * 16);
            LDSM4(b01[0], b01[1], b01[2], b01[3], kst + rowk * 80 + (2 + chk) * 16);

            uint32_t A[2][4];   // P in fp16 A-frag layout, per m-tile
            #pragma unroll
            for (int mt = 0; mt < 2; mt++) {
                #pragma unroll
                for (int h = 0; h < 2; h++) {
                    float s4[4] = {0.f, 0.f, 0.f, 0.f};
                    MMA16816(s4, qa[mt][0][0], qa[mt][0][1], qa[mt][0][2], qa[mt][0][3], b00[2*h], b00[2*h+1]);
                    MMA16816(s4, qa[mt][1][0], qa[mt][1][1], qa[mt][1][2], qa[mt][1][3], b01[2*h], b01[2*h+1]);
                    A[mt][2*h]   = ex2_h2(pack_f16x2(s4[1], s4[0]));
                    A[mt][2*h+1] = ex2_h2(pack_f16x2(s4[3], s4[2]));
                }
                float2 f0 = h2_to_f2(hadd2(A[mt][0], A[mt][2]));
                lsum[mt][0] += f0.x + f0.y;
                float2 f1 = h2_to_f2(hadd2(A[mt][1], A[mt][3]));
                lsum[mt][1] += f1.x + f1.y;
            }

            uint32_t rowv = g * 16 + (lane & 7) + ((lane >> 3) & 1) * 8;
            uint32_t chv = lane >> 4;
            uint32_t v0[4], v1[4];
            LDSM4T(v0[0], v0[1], v0[2], v0[3], vst + rowv * 80 + chv * 16);
            LDSM4T(v1[0], v1[1], v1[2], v1[3], vst + rowv * 80 + (2 + chv) * 16);
            #pragma unroll
            for (int mt = 0; mt < 2; mt++) {
                MMA16816(o[mt][0], A[mt][0], A[mt][1], A[mt][2], A[mt][3], v0[0], v0[1]);
                MMA16816(o[mt][1], A[mt][0], A[mt][1], A[mt][2], A[mt][3], v0[2], v0[3]);
                MMA16816(o[mt][2], A[mt][0], A[mt][1], A[mt][2], A[mt][3], v1[0], v1[1]);
                MMA16816(o[mt][3], A[mt][0], A[mt][1], A[mt][2], A[mt][3], v1[2], v1[3]);
            }
        }
    }

    // ---- epilogue: row-sum reduce, normalize, residual, write ----
    #pragma unroll
    for (int mt = 0; mt < 2; mt++) {
        float l0 = lsum[mt][0];
        l0 += __shfl_xor_sync(0xffffffffu, l0, 1);
        l0 += __shfl_xor_sync(0xffffffffu, l0, 2);
        float l1 = lsum[mt][1];
        l1 += __shfl_xor_sync(0xffffffffu, l1, 1);
        l1 += __shfl_xor_sync(0xffffffffu, l1, 2);
        float inv0 = 1.0f / l0, inv1 = 1.0f / l1;

        int r0 = q0 + 32 * wid + 16 * mt + (lane >> 2);
        size_t base0 = (size_t)b * (CEMB * NTOK) + (size_t)r0 * CEMB + head * HD;
        size_t base1 = base0 + (size_t)8 * CEMB;

        #pragma unroll
        for (int nt = 0; nt < 4; nt++) {
            int col = 8 * nt + (lane & 3) * 2;
            float2 xv0 = *(const float2*)(x + base0 + col);
            float2 r;
            r.x = fmaf(o[mt][nt][0], inv0, xv0.x);
            r.y = fmaf(o[mt][nt][1], inv0, xv0.y);
            *(float2*)(out + base0 + col) = r;
            float2 xv1 = *(const float2*)(x + base1 + col);
            r.x = fmaf(o[mt][nt][2], inv1, xv1.x);
            r.y = fmaf(o[mt][nt][3], inv1, xv1.y);
            *(float2*)(out + base1 + col) = r;
        }
    }
}

extern "C" void kernel_launch(void* const* d_in, const int* in_sizes, int n_in,
                              void* d_out, int out_size) {
    const float* x    = (const float*)d_in[0];
    const float* W    = (const float*)d_in[1];
    const float* bias = (const float*)d_in[2];
    float* out = (float*)d_out;

    dim3 g1(3, 32, NB);
    qkv_kernel<<<g1, 256>>>(x, W, bias);

    dim3 g2(NTOK / 128, NBH);
    attn_kernel<<<g2, 128>>>(x, out);
}